// round 6
// baseline (speedup 1.0000x reference)
#include <cuda_runtime.h>
#include <cuda_bf16.h>
#include <cstdint>
#include <cstring>

// Problem: N=32768 points, K=8192 centers, D=32. fp32 in, labels-as-fp32 out.
#define DIMS      32
#define NPOINTS   32768
#define KCENT     8192
#define KSTEPS    12            // 192 expanded K / 16 per mma
#define ROWB      384           // bytes per expanded row (192 bf16)
#define ROWW      96            // words per expanded row
#define PITCH     400           // smem row pitch (400 mod 128 = 16 -> conflict-free ldmatrix)
#define TILE_N    128           // centers per smem tile
#define NTILES    (KCENT / TILE_N)   // 64
#define THREADS   256           // 8 warps x 32 points = 256 points/CTA
#define GRID      128           // 128 * 256 = 32768 exactly

// smem layout (dynamic): B tiles double-buffered + c2 tiles
#define SM_B(s)   ((s) * (TILE_N * PITCH))          // 0 / 51200
#define SM_C2(s)  (102400 + (s) * 512)
#define SMEM_TOTAL 103424

// ---- pre-expanded operands (allocation-free: __device__ globals) ----
__device__ __align__(16) uint8_t g_aexp[(size_t)NPOINTS * ROWB];  // 12.6 MB
__device__ __align__(16) uint8_t g_bexp[(size_t)KCENT * ROWB];    // 3.1 MB
__device__ float g_c2[KCENT];

// ---- split fp32 into 3 bf16 limbs ----
__device__ __forceinline__ void split3(float v, float& f0, float& f1, float& f2) {
    f0 = __bfloat162float(__float2bfloat16(v));
    float r1 = v - f0;
    f1 = __bfloat162float(__float2bfloat16(r1));
    float r2 = r1 - f1;
    f2 = __bfloat162float(__float2bfloat16(r2));
}
__device__ __forceinline__ uint32_t pack_bf2(float lo, float hi) {
    __nv_bfloat162 h = __floats2bfloat162_rn(lo, hi);
    uint32_t u; memcpy(&u, &h, 4); return u;
}

// ---- prep: expand points ----
__global__ void prep_points(const float* __restrict__ x, int N) {
    int p = blockIdx.x * blockDim.x + threadIdx.x;
    if (p >= N) return;
    float s0[DIMS], s1[DIMS], s2[DIMS];
    const float4* row = reinterpret_cast<const float4*>(x + (size_t)p * DIMS);
#pragma unroll
    for (int q = 0; q < DIMS / 4; q++) {
        float4 v = row[q];
        split3(v.x, s0[4*q+0], s1[4*q+0], s2[4*q+0]);
        split3(v.y, s0[4*q+1], s1[4*q+1], s2[4*q+1]);
        split3(v.z, s0[4*q+2], s1[4*q+2], s2[4*q+2]);
        split3(v.w, s0[4*q+3], s1[4*q+3], s2[4*q+3]);
    }
    uint32_t w[ROWW];
    const float* segs[6] = { s0, s0, s1, s1, s0, s2 };   // A: [a0,a0,a1,a1,a0,a2]
#pragma unroll
    for (int s = 0; s < 6; s++)
#pragma unroll
        for (int d = 0; d < 16; d++)
            w[s * 16 + d] = pack_bf2(segs[s][2*d], segs[s][2*d+1]);
    uint4* dst = reinterpret_cast<uint4*>(g_aexp + (size_t)p * ROWB);
#pragma unroll
    for (int i = 0; i < ROWW / 4; i++)
        dst[i] = make_uint4(w[4*i], w[4*i+1], w[4*i+2], w[4*i+3]);
}

// ---- prep: expand centers + ||c||^2 ----
__global__ void prep_centers(const float* __restrict__ c, int K) {
    int k = blockIdx.x * blockDim.x + threadIdx.x;
    if (k >= K) return;
    float s0[DIMS], s1[DIMS], s2[DIMS];
    float c2 = 0.0f;
    const float4* row = reinterpret_cast<const float4*>(c + (size_t)k * DIMS);
#pragma unroll
    for (int q = 0; q < DIMS / 4; q++) {
        float4 v = row[q];
        split3(v.x, s0[4*q+0], s1[4*q+0], s2[4*q+0]);
        split3(v.y, s0[4*q+1], s1[4*q+1], s2[4*q+1]);
        split3(v.z, s0[4*q+2], s1[4*q+2], s2[4*q+2]);
        split3(v.w, s0[4*q+3], s1[4*q+3], s2[4*q+3]);
        c2 = fmaf(v.x, v.x, c2); c2 = fmaf(v.y, v.y, c2);
        c2 = fmaf(v.z, v.z, c2); c2 = fmaf(v.w, v.w, c2);
    }
    uint32_t w[ROWW];
    const float* segs[6] = { s0, s1, s0, s1, s2, s0 };   // B: [b0,b1,b0,b1,b2,b0]
#pragma unroll
    for (int s = 0; s < 6; s++)
#pragma unroll
        for (int d = 0; d < 16; d++)
            w[s * 16 + d] = pack_bf2(segs[s][2*d], segs[s][2*d+1]);
    uint4* dst = reinterpret_cast<uint4*>(g_bexp + (size_t)k * ROWB);
#pragma unroll
    for (int i = 0; i < ROWW / 4; i++)
        dst[i] = make_uint4(w[4*i], w[4*i+1], w[4*i+2], w[4*i+3]);
    g_c2[k] = c2;
}

// ---- ptx helpers ----
__device__ __forceinline__ uint32_t smem_u32(const void* p) {
    uint32_t a;
    asm("{ .reg .u64 t; cvta.to.shared.u64 t, %1; cvt.u32.u64 %0, t; }" : "=r"(a) : "l"(p));
    return a;
}
__device__ __forceinline__ void cp16(uint32_t dst, const void* src) {
    asm volatile("cp.async.cg.shared.global [%0], [%1], 16;" :: "r"(dst), "l"(src) : "memory");
}
#define MMA16816(d0,d1,d2,d3,a0,a1,a2,a3,b0,b1) \
    asm volatile("mma.sync.aligned.m16n8k16.row.col.f32.bf16.bf16.f32 " \
                 "{%0,%1,%2,%3}, {%4,%5,%6,%7}, {%8,%9}, {%0,%1,%2,%3};" \
                 : "+f"(d0), "+f"(d1), "+f"(d2), "+f"(d3) \
                 : "r"(a0), "r"(a1), "r"(a2), "r"(a3), "r"(b0), "r"(b1))

// ---- main: mma.sync GEMM + fused argmin ----
__global__ __launch_bounds__(THREADS, 1)
void tc_label(float* __restrict__ out) {
    extern __shared__ uint8_t smem[];
    const uint32_t sb = smem_u32(smem);
    const int tid = threadIdx.x, lane = tid & 31, warp = tid >> 5;
    const int lm4 = lane & 3;
    const int pbase = blockIdx.x * 256 + warp * 32;

    // Two resident A-sets: A0 = points pbase..+15, A1 = pbase+16..+31.
    uint32_t A0[KSTEPS][4], A1[KSTEPS][4];
    {
        const uint32_t* r0 = reinterpret_cast<const uint32_t*>(g_aexp + (size_t)(pbase + (lane >> 2)) * ROWB);
        const uint32_t* r1 = reinterpret_cast<const uint32_t*>(g_aexp + (size_t)(pbase + (lane >> 2) + 8) * ROWB);
        const uint32_t* r2 = reinterpret_cast<const uint32_t*>(g_aexp + (size_t)(pbase + 16 + (lane >> 2)) * ROWB);
        const uint32_t* r3 = reinterpret_cast<const uint32_t*>(g_aexp + (size_t)(pbase + 16 + (lane >> 2) + 8) * ROWB);
#pragma unroll
        for (int s = 0; s < KSTEPS; s++) {
            A0[s][0] = r0[s * 8 + lm4];     A0[s][1] = r1[s * 8 + lm4];
            A0[s][2] = r0[s * 8 + 4 + lm4]; A0[s][3] = r1[s * 8 + 4 + lm4];
            A1[s][0] = r2[s * 8 + lm4];     A1[s][1] = r3[s * 8 + lm4];
            A1[s][2] = r2[s * 8 + 4 + lm4]; A1[s][3] = r3[s * 8 + 4 + lm4];
        }
    }

    const float FLTMAX = 3.402823466e38f;
    float bv[4] = { FLTMAX, FLTMAX, FLTMAX, FLTMAX };  // A0:r, A0:r+8, A1:r, A1:r+8
    int   bi[4] = { 0, 0, 0, 0 };

    // tile loader: 128 rows x 24 chunks + 32 c2 chunks = 3104 x 16B
    auto issue = [&](int t) {
        const uint32_t dstB = sb + SM_B(t & 1);
        const uint32_t dstC = sb + SM_C2(t & 1);
        const uint8_t* srcB = g_bexp + (size_t)t * TILE_N * ROWB;
        const uint8_t* srcC = reinterpret_cast<const uint8_t*>(g_c2 + t * TILE_N);
        for (int i = tid; i < 3104; i += THREADS) {
            if (i < 3072) {
                int row = i / 24, ch = i % 24;
                cp16(dstB + row * PITCH + ch * 16, srcB + row * ROWB + ch * 16);
            } else {
                int j = i - 3072;
                cp16(dstC + j * 16, srcC + j * 16);
            }
        }
        asm volatile("cp.async.commit_group;" ::: "memory");
    };

    issue(0);
    issue(1);

    // ldmatrix.x4 source: threads 0-7 rows 0-7 @+0 (k0..7), 8-15 @+16 (k8..15),
    // 16-23 @+32 (next kstep k0..7), 24-31 @+48.
    const uint32_t lmoff = (uint32_t)(lane & 7) * PITCH + (uint32_t)(lane >> 3) * 16;

    for (int t = 0; t < NTILES; t++) {
        if (t < NTILES - 1) asm volatile("cp.async.wait_group 1;" ::: "memory");
        else                asm volatile("cp.async.wait_group 0;" ::: "memory");
        __syncthreads();

        const uint32_t bufB = sb + SM_B(t & 1);
        const float* c2s = reinterpret_cast<const float*>(smem + SM_C2(t & 1));
        const int kb = t * TILE_N;

#pragma unroll 2
        for (int blk = 0; blk < TILE_N / 8; blk++) {
            const uint32_t ba = bufB + (uint32_t)blk * (8 * PITCH) + lmoff;
            // 4 independent accumulator chains: {A0,A1} x {even,odd ksteps}
            float e0[4] = {0,0,0,0}, o0[4] = {0,0,0,0};
            float e1[4] = {0,0,0,0}, o1[4] = {0,0,0,0};
#pragma unroll
            for (int sp = 0; sp < KSTEPS / 2; sp++) {
                uint32_t b0, b1, b2, b3;
                asm volatile("ldmatrix.sync.aligned.m8n8.x4.shared.b16 {%0,%1,%2,%3}, [%4];"
                             : "=r"(b0), "=r"(b1), "=r"(b2), "=r"(b3) : "r"(ba + sp * 64));
                const int s0 = 2 * sp, s1 = 2 * sp + 1;
                MMA16816(e0[0], e0[1], e0[2], e0[3], A0[s0][0], A0[s0][1], A0[s0][2], A0[s0][3], b0, b1);
                MMA16816(e1[0], e1[1], e1[2], e1[3], A1[s0][0], A1[s0][1], A1[s0][2], A1[s0][3], b0, b1);
                MMA16816(o0[0], o0[1], o0[2], o0[3], A0[s1][0], A0[s1][1], A0[s1][2], A0[s1][3], b2, b3);
                MMA16816(o1[0], o1[1], o1[2], o1[3], A1[s1][0], A1[s1][1], A1[s1][2], A1[s1][3], b2, b3);
            }
            const int ci = blk * 8 + lm4 * 2;
            const float c2a = c2s[ci], c2b = c2s[ci + 1];
            const int idx = kb + ci;
            // combine chains, finish score = c2 - 2*dot
            float v;
            v = fmaf(-2.0f, e0[0] + o0[0], c2a); if (v < bv[0]) { bv[0] = v; bi[0] = idx; }
            v = fmaf(-2.0f, e0[1] + o0[1], c2b); if (v < bv[0]) { bv[0] = v; bi[0] = idx + 1; }
            v = fmaf(-2.0f, e0[2] + o0[2], c2a); if (v < bv[1]) { bv[1] = v; bi[1] = idx; }
            v = fmaf(-2.0f, e0[3] + o0[3], c2b); if (v < bv[1]) { bv[1] = v; bi[1] = idx + 1; }
            v = fmaf(-2.0f, e1[0] + o1[0], c2a); if (v < bv[2]) { bv[2] = v; bi[2] = idx; }
            v = fmaf(-2.0f, e1[1] + o1[1], c2b); if (v < bv[2]) { bv[2] = v; bi[2] = idx + 1; }
            v = fmaf(-2.0f, e1[2] + o1[2], c2a); if (v < bv[3]) { bv[3] = v; bi[3] = idx; }
            v = fmaf(-2.0f, e1[3] + o1[3], c2b); if (v < bv[3]) { bv[3] = v; bi[3] = idx + 1; }
        }
        __syncthreads();
        if (t + 2 < NTILES) issue(t + 2);
    }

    // reduce across the 4 threads sharing each row (ties -> lower index)
#pragma unroll
    for (int q = 0; q < 4; q++) {
#pragma unroll
        for (int off = 1; off < 4; off <<= 1) {
            float ov = __shfl_xor_sync(0xFFFFFFFFu, bv[q], off);
            int   oi = __shfl_xor_sync(0xFFFFFFFFu, bi[q], off);
            if (ov < bv[q] || (ov == bv[q] && oi < bi[q])) { bv[q] = ov; bi[q] = oi; }
        }
    }
    if (lm4 == 0) {
        const int r = lane >> 2;
        out[pbase + r]      = (float)bi[0];
        out[pbase + r + 8]  = (float)bi[1];
        out[pbase + 16 + r] = (float)bi[2];
        out[pbase + 24 + r] = (float)bi[3];
    }
}

extern "C" void kernel_launch(void* const* d_in, const int* in_sizes, int n_in,
                              void* d_out, int out_size) {
    const float* x; const float* c; int nx, nc;
    if (in_sizes[0] >= in_sizes[1]) { x = (const float*)d_in[0]; nx = in_sizes[0];
                                      c = (const float*)d_in[1]; nc = in_sizes[1]; }
    else                            { x = (const float*)d_in[1]; nx = in_sizes[1];
                                      c = (const float*)d_in[0]; nc = in_sizes[0]; }
    float* out = (float*)d_out;
    int N = nx / DIMS;   // 32768
    int K = nc / DIMS;   // 8192

    prep_points <<<(N + 127) / 128, 128>>>(x, N);
    prep_centers<<<(K + 127) / 128, 128>>>(c, K);

    cudaFuncSetAttribute(tc_label, cudaFuncAttributeMaxDynamicSharedMemorySize, SMEM_TOTAL);
    tc_label<<<GRID, THREADS, SMEM_TOTAL>>>(out);
}